// round 16
// baseline (speedup 1.0000x reference)
#include <cuda_runtime.h>
#include <cuda_bf16.h>
#include <cuda_fp16.h>
#include <math.h>
#include <cstdint>

#define Bq   8
#define Tq   2048
#define Dq   1024
#define HSq  128
#define BT   (Bq * Tq)        // 16384 rows
#define NTOT 384              // 3 * HS

#define N_PROJ_JOBS 768       // 8 batches x 16 Mtiles x 6 slab-halves
#define N_ATTN_JOBS 384       // 8 batches x 48 chunks
#define GRID_MEGA   304

// Scratch (device globals — no allocs allowed). All operands single fp16.
__device__ __align__(256) __half g_x_h[BT * Dq];             // x single fp16
__device__ __align__(256) __half g_wt_h[NTOT * Dq];          // W^T fp16 (Wq pre-scaled)
__device__ __align__(256) __half g_q[BT * HSq];
__device__ __align__(256) __half g_k[BT * HSq];
__device__ __align__(256) __half g_v[BT * HSq];

// Split-KV partials: [b][qt][part][64][128] fp32 + per-row m,l (base-2 logits)
__device__ __align__(256) float g_po[Bq * 32 * 2 * 64 * 128];
__device__ __align__(256) float g_pm[Bq * 32 * 2 * 64];
__device__ __align__(256) float g_pl[Bq * 32 * 2 * 64];

// Work-queue state (zeroed each launch by zero_kernel)
__device__ unsigned g_proj_ctr;
__device__ unsigned g_attn_ctr;
__device__ unsigned g_proj_done[Bq];

// Chunk LUT (48 chunks per batch), heavy-first (cnt descending).
__device__ const int c_qt[48]  = {15,16,17,18,19,20,21,22,23,24,25,26,27,28,29,30,31,31,
                                  14,30,13,29,12,28,11,27,10,26, 9,25, 8,24, 7,23,
                                   6,22, 5,21, 4,20, 3,19, 2,18, 1,17, 0,16};
__device__ const int c_k0[48]  = { 0, 0, 0, 0, 0, 0, 0, 0, 0, 0, 0, 0, 0, 0, 0, 0, 0,16,
                                   0,16, 0,16, 0,16, 0,16, 0,16, 0,16, 0,16, 0,16,
                                   0,16, 0,16, 0,16, 0,16, 0,16, 0,16, 0,16};
__device__ const int c_cnt[48] = {16,16,16,16,16,16,16,16,16,16,16,16,16,16,16,16,16,16,
                                  15,15,14,14,13,13,12,12,11,11,10,10, 9, 9, 8, 8,
                                   7, 7, 6, 6, 5, 5, 4, 4, 3, 3, 2, 2, 1, 1};

// ---------------------------------------------------------------------------
// Helpers
// ---------------------------------------------------------------------------
__device__ __forceinline__ void mma_f16(float* c, const uint32_t* a, const uint32_t* b) {
    asm volatile(
        "mma.sync.aligned.m16n8k16.row.col.f32.f16.f16.f32 "
        "{%0,%1,%2,%3}, {%4,%5,%6,%7}, {%8,%9}, {%0,%1,%2,%3};"
        : "+f"(c[0]), "+f"(c[1]), "+f"(c[2]), "+f"(c[3])
        : "r"(a[0]), "r"(a[1]), "r"(a[2]), "r"(a[3]), "r"(b[0]), "r"(b[1]));
}
__device__ __forceinline__ void ldsm_x4(uint32_t* r, uint32_t addr) {
    asm volatile("ldmatrix.sync.aligned.m8n8.x4.shared.b16 {%0,%1,%2,%3}, [%4];"
                 : "=r"(r[0]), "=r"(r[1]), "=r"(r[2]), "=r"(r[3]) : "r"(addr));
}
__device__ __forceinline__ void ldsm_x4_t(uint32_t* r, uint32_t addr) {
    asm volatile("ldmatrix.sync.aligned.m8n8.x4.trans.shared.b16 {%0,%1,%2,%3}, [%4];"
                 : "=r"(r[0]), "=r"(r[1]), "=r"(r[2]), "=r"(r[3]) : "r"(addr));
}
__device__ __forceinline__ uint32_t smem_u32(const void* p) {
    uint32_t a;
    asm("{ .reg .u64 t; cvta.to.shared.u64 t, %1; cvt.u32.u64 %0, t; }"
        : "=r"(a) : "l"(p));
    return a;
}
__device__ __forceinline__ void cp16(uint32_t dst, const void* src) {
    asm volatile("cp.async.cg.shared.global [%0], [%1], 16;" :: "r"(dst), "l"(src));
}
#define CP_COMMIT() asm volatile("cp.async.commit_group;" ::: "memory")
#define CP_WAIT0()  asm volatile("cp.async.wait_group 0;" ::: "memory")
#define CP_WAIT1()  asm volatile("cp.async.wait_group 1;" ::: "memory")

__device__ __forceinline__ uint32_t packh2(float v0, float v1) {
    __half2 h2 = __floats2half2_rn(v0, v1);
    return *(uint32_t*)&h2;
}

// ---------------------------------------------------------------------------
// Kernel Z: zero the work-queue state (must run each launch / graph replay).
// ---------------------------------------------------------------------------
__global__ void zero_kernel()
{
    if (threadIdx.x == 0) { g_proj_ctr = 0; g_attn_ctr = 0; }
    if (threadIdx.x < Bq) g_proj_done[threadIdx.x] = 0;
}

// ---------------------------------------------------------------------------
// Kernel 0a: convert x -> single fp16. 8 floats per thread.
// ---------------------------------------------------------------------------
__global__ __launch_bounds__(256) void prep_x_kernel(const float* __restrict__ x)
{
    size_t i = ((size_t)blockIdx.x * 256 + threadIdx.x) * 8;
    float4 a = *(const float4*)&x[i];
    float4 b = *(const float4*)&x[i + 4];
    *(uint4*)&g_x_h[i] = make_uint4(packh2(a.x, a.y), packh2(a.z, a.w),
                                    packh2(b.x, b.y), packh2(b.z, b.w));
}

// ---------------------------------------------------------------------------
// Kernel 0b: transpose + convert weights to fp16 (Wq scaled by 128^-0.5*log2e).
// ---------------------------------------------------------------------------
__global__ void prep_w_kernel(const float* __restrict__ Wq,
                              const float* __restrict__ Wk,
                              const float* __restrict__ Wv)
{
    __shared__ float t[32][33];
    const int k0 = blockIdx.x * 32;
    const int n0 = blockIdx.y * 32;
    const int slab = n0 >> 7;
    const float* W = (slab == 0) ? Wq : (slab == 1) ? Wk : Wv;
    const float sc = (slab == 0) ? (0.08838834764831845f * 1.4426950408889634f) : 1.0f;
    const int nn0 = n0 & 127;
    const int tx = threadIdx.x, ty = threadIdx.y;

    #pragma unroll
    for (int i = 0; i < 4; i++)
        t[ty * 4 + i][tx] = W[(size_t)(k0 + ty * 4 + i) * HSq + nn0 + tx] * sc;
    __syncthreads();
    #pragma unroll
    for (int i = 0; i < 4; i++) {
        int nr = ty * 4 + i;
        g_wt_h[(size_t)(n0 + nr) * Dq + k0 + tx] = __float2half_rn(t[tx][nr]);
    }
}

// ---------------------------------------------------------------------------
// Megakernel: persistent blocks, dynamic queues.
// Phase 1: proj jobs (BM=128, BN=64, BK=64, 4 warps). 768 jobs batch-major.
// Phase 2: attn chunks (R15 body). Spin on per-batch proj completion.
// smem: proj 2*(128+64)*144 = 55296; attn 3*17408 = 52224. Dyn smem 55296.
// ---------------------------------------------------------------------------
#define PS      144           // proj smem row pitch bytes (64 fp16 + 8 pad)
#define PJ_X    0
#define PJ_W    (128 * PS)                 // 18432
#define PJ_BUF  (PJ_W + 64 * PS)           // 27648
#define MEGA_SMEM (2 * PJ_BUF)             // 55296

#define KV_ROWB 272                        // attn: 128 fp16 + 8 pad
#define KTILE   (64 * KV_ROWB)             // 17408
#define A_K0    0
#define A_K1    (1 * KTILE)
#define A_V     (2 * KTILE)

__global__ __launch_bounds__(128, 2) void mega_kernel(float* __restrict__ out)
{
    extern __shared__ __align__(16) char smc[];
    __shared__ int s_job;
    const uint32_t sb = smem_u32(smc);
    const int tid = threadIdx.x;
    const int w   = tid >> 5;
    const int L   = tid & 31;
    const int lr  = L >> 2;
    const int lc  = (L & 3) * 2;

    // ============================ Phase 1: projection =====================
    for (;;) {
        if (tid == 0) s_job = (int)atomicAdd(&g_proj_ctr, 1u);
        __syncthreads();
        const int j = s_job;
        if (j >= N_PROJ_JOBS) break;

        const int b  = j / 96;
        const int r  = j % 96;
        const int mi = r & 15;
        const int s  = r >> 4;            // 0..5 slab-half
        const int nt = s >> 1;            // 0:q 1:k 2:v
        const int ncol0 = (s & 1) * 64;
        const int m0 = (b * 16 + mi) * 128;

        const __half* wh = g_wt_h + ((size_t)nt * HSq + ncol0) * Dq;
        const __half* xh = g_x_h + (size_t)m0 * Dq;
        __half* outp = (nt == 0) ? g_q : (nt == 1) ? g_k : g_v;

        const int mrow = w * 32;

        float c[2][8][4];
        #pragma unroll
        for (int mt = 0; mt < 2; mt++)
            #pragma unroll
            for (int jn = 0; jn < 8; jn++)
                #pragma unroll
                for (int rr = 0; rr < 4; rr++) c[mt][jn][rr] = 0.f;

        auto prefetch = [&](int ch, uint32_t bb) {
            const int kb = ch * 64;
            #pragma unroll
            for (int i = 0; i < 8; i++) {         // X: 128 rows x 8 x16B
                int idx = tid + i * 128;
                int rr = idx >> 3, q = idx & 7;
                cp16(bb + PJ_X + rr * PS + q * 16, xh + (size_t)rr * Dq + kb + q * 8);
            }
            #pragma unroll
            for (int i = 0; i < 4; i++) {         // W: 64 rows x 8 x16B
                int idx = tid + i * 128;
                int rr = idx >> 3, q = idx & 7;
                cp16(bb + PJ_W + rr * PS + q * 16, wh + (size_t)rr * Dq + kb + q * 8);
            }
        };

        prefetch(0, sb);
        CP_COMMIT();

        for (int ch = 0; ch < Dq / 64; ch++) {
            if (ch + 1 < Dq / 64) prefetch(ch + 1, sb + ((ch + 1) & 1) * PJ_BUF);
            CP_COMMIT();
            CP_WAIT1();
            __syncthreads();

            const uint32_t base = sb + (ch & 1) * PJ_BUF;

            uint32_t ah[2][4][4];
            #pragma unroll
            for (int mt = 0; mt < 2; mt++) {
                uint32_t arow = base + PJ_X
                    + (uint32_t)(mrow + mt * 16 + (L & 7) + ((L >> 3) & 1) * 8) * PS
                    + (L >> 4) * 16;
                #pragma unroll
                for (int ks = 0; ks < 4; ks++)
                    ldsm_x4(ah[mt][ks], arow + ks * 32);
            }

            #pragma unroll
            for (int jn = 0; jn < 8; jn++) {
                uint32_t brow = base + PJ_W
                    + (uint32_t)(8 * jn + (L & 7)) * PS + ((L >> 3) & 3) * 16;
                uint32_t bh[4], bh2[4];
                ldsm_x4(bh, brow);          // k 0-31
                ldsm_x4(bh2, brow + 64);    // k 32-63
                #pragma unroll
                for (int mt = 0; mt < 2; mt++) {
                    mma_f16(c[mt][jn], ah[mt][0], bh);
                    mma_f16(c[mt][jn], ah[mt][1], bh + 2);
                    mma_f16(c[mt][jn], ah[mt][2], bh2);
                    mma_f16(c[mt][jn], ah[mt][3], bh2 + 2);
                }
            }
            __syncthreads();
        }

        // Epilogue: single fp16 pack
        #pragma unroll
        for (int mt = 0; mt < 2; mt++) {
            int r0 = m0 + mrow + mt * 16 + lr;
            #pragma unroll
            for (int jn = 0; jn < 8; jn++) {
                int cc = ncol0 + 8 * jn + lc;
                *(uint32_t*)&outp[(size_t)r0 * HSq + cc] = packh2(c[mt][jn][0], c[mt][jn][1]);
                *(uint32_t*)&outp[(size_t)(r0 + 8) * HSq + cc] = packh2(c[mt][jn][2], c[mt][jn][3]);
            }
        }

        __syncthreads();
        if (tid == 0) {
            __threadfence();
            atomicAdd(&g_proj_done[b], 1u);
        }
    }

    // ============================ Phase 2: attention ======================
    for (;;) {
        if (tid == 0) s_job = (int)atomicAdd(&g_attn_ctr, 1u);
        __syncthreads();
        const int j = s_job;
        if (j >= N_ATTN_JOBS) break;

        const int b   = j / 48;
        const int cid = j % 48;
        const int qt  = c_qt[cid];
        const int kt0 = c_k0[cid];
        const int cnt = c_cnt[cid];
        const int q0  = qt * 64;

        // Wait for this batch's projection to complete.
        if (tid == 0) {
            while (atomicAdd(&g_proj_done[b], 0u) < 96u) { }
        }
        __syncthreads();
        __threadfence();   // gpu-scope fence -> L1 invalidate (fresh q/k/v)

        const __half* q_g = g_q + (size_t)b * Tq * HSq;
        const __half* k_g = g_k + (size_t)b * Tq * HSq;
        const __half* v_g = g_v + (size_t)b * Tq * HSq;

        auto prefetch_k = [&](int krow, int buf) {
            uint32_t kb = sb + (buf ? A_K1 : A_K0);
            #pragma unroll
            for (int i = 0; i < 8; i++) {
                int idx = tid + i * 128;
                int rr = idx >> 4, q = idx & 15;
                cp16(kb + rr * KV_ROWB + q * 16, k_g + (size_t)(krow + rr) * HSq + q * 8);
            }
        };
        auto prefetch_v = [&](int krow) {
            #pragma unroll
            for (int i = 0; i < 8; i++) {
                int idx = tid + i * 128;
                int rr = idx >> 4, q = idx & 15;
                cp16(sb + A_V + rr * KV_ROWB + q * 16, v_g + (size_t)(krow + rr) * HSq + q * 8);
            }
        };

        // Q fragments (pre-scaled by 128^-0.5*log2e), single fp16
        uint32_t qh[8][4];
        #pragma unroll
        for (int sfs = 0; sfs < 8; sfs++)
            #pragma unroll
            for (int i = 0; i < 4; i++) {
                int rr = q0 + 16 * w + lr + 8 * (i & 1);
                int cc = 16 * sfs + lc + 8 * (i >> 1);
                qh[sfs][i] = *(const uint32_t*)&q_g[(size_t)rr * HSq + cc];
            }

        float o[16][4];
        #pragma unroll
        for (int jj = 0; jj < 16; jj++)
            #pragma unroll
            for (int rr = 0; rr < 4; rr++) o[jj][rr] = 0.f;
        float m0v = -1e30f, m1v = -1e30f, l0v = 0.f, l1v = 0.f;

        prefetch_k(kt0 * 64, 0); CP_COMMIT();
        prefetch_v(kt0 * 64);    CP_COMMIT();

        for (int t = 0; t < cnt; t++) {
            const int tile = kt0 + t;
            CP_WAIT1();
            __syncthreads();
            if (t + 1 < cnt) { prefetch_k((tile + 1) * 64, (t + 1) & 1); CP_COMMIT(); }

            const uint32_t kbuf = sb + ((t & 1) ? A_K1 : A_K0);

            // S = Q K^T
            float c[8][4];
            #pragma unroll
            for (int jn = 0; jn < 8; jn++) {
                c[jn][0] = c[jn][1] = c[jn][2] = c[jn][3] = 0.f;
                uint32_t rowaddr = kbuf + (8 * jn + (L & 7)) * KV_ROWB + ((L >> 3) & 3) * 16;
                #pragma unroll
                for (int sp = 0; sp < 4; sp++) {
                    uint32_t bh[4];
                    ldsm_x4(bh, rowaddr + 64 * sp);
                    mma_f16(c[jn], qh[2 * sp],     bh);
                    mma_f16(c[jn], qh[2 * sp + 1], bh + 2);
                }
            }

            // Causal mask on diagonal tile
            if (tile == qt) {
                int r0 = 16 * w + lr, r1 = r0 + 8;
                #pragma unroll
                for (int jn = 0; jn < 8; jn++) {
                    int n0 = 8 * jn + lc;
                    if (n0 > r0)     c[jn][0] = -1e30f;
                    if (n0 + 1 > r0) c[jn][1] = -1e30f;
                    if (n0 > r1)     c[jn][2] = -1e30f;
                    if (n0 + 1 > r1) c[jn][3] = -1e30f;
                }
            }

            // Online softmax (base-2)
            float mx0 = -1e30f, mx1 = -1e30f;
            #pragma unroll
            for (int jn = 0; jn < 8; jn++) {
                mx0 = fmaxf(mx0, fmaxf(c[jn][0], c[jn][1]));
                mx1 = fmaxf(mx1, fmaxf(c[jn][2], c[jn][3]));
            }
            #pragma unroll
            for (int off = 1; off <= 2; off <<= 1) {
                mx0 = fmaxf(mx0, __shfl_xor_sync(0xffffffffu, mx0, off));
                mx1 = fmaxf(mx1, __shfl_xor_sync(0xffffffffu, mx1, off));
            }
            float mn0 = fmaxf(m0v, mx0), mn1 = fmaxf(m1v, mx1);
            float a0 = exp2f(m0v - mn0), a1 = exp2f(m1v - mn1);
            float rs0 = 0.f, rs1 = 0.f;
            uint32_t ph[8][2];
            #pragma unroll
            for (int jn = 0; jn < 8; jn++) {
                float p0 = exp2f(c[jn][0] - mn0);
                float p1 = exp2f(c[jn][1] - mn0);
                float p2 = exp2f(c[jn][2] - mn1);
                float p3 = exp2f(c[jn][3] - mn1);
                rs0 += p0 + p1; rs1 += p2 + p3;
                ph[jn][0] = packh2(p0, p1);
                ph[jn][1] = packh2(p2, p3);
            }
            #pragma unroll
            for (int off = 1; off <= 2; off <<= 1) {
                rs0 += __shfl_xor_sync(0xffffffffu, rs0, off);
                rs1 += __shfl_xor_sync(0xffffffffu, rs1, off);
            }
            l0v = l0v * a0 + rs0;  m0v = mn0;
            l1v = l1v * a1 + rs1;  m1v = mn1;
            #pragma unroll
            for (int jj = 0; jj < 16; jj++) {
                o[jj][0] *= a0; o[jj][1] *= a0;
                o[jj][2] *= a1; o[jj][3] *= a1;
            }

            if (t + 1 < cnt) { CP_WAIT1(); } else { CP_WAIT0(); }
            __syncthreads();

            // O += P V
            #pragma unroll
            for (int sp = 0; sp < 4; sp++) {
                uint32_t ap[4] = { ph[2*sp][0], ph[2*sp][1], ph[2*sp+1][0], ph[2*sp+1][1] };
                uint32_t vaddr = sb + A_V + (16 * sp + (L & 15)) * KV_ROWB + (L >> 4) * 16;
                #pragma unroll
                for (int jj = 0; jj < 16; jj += 2) {
                    uint32_t bh[4];
                    ldsm_x4_t(bh, vaddr + 16 * jj);
                    mma_f16(o[jj],     ap, bh);
                    mma_f16(o[jj + 1], ap, bh + 2);
                }
            }

            __syncthreads();
            if (t + 1 < cnt) { prefetch_v((tile + 1) * 64); CP_COMMIT(); }
        }

        const bool full = (kt0 == 0) && (cnt == qt + 1);
        int r0 = 16 * w + lr;
        if (full) {
            float inv0 = __frcp_rn(l0v), inv1 = __frcp_rn(l1v);
            #pragma unroll
            for (int jj = 0; jj < 16; jj++) {
                int cc = 8 * jj + lc;
                *(float2*)&out[((size_t)b * Tq + q0 + r0) * HSq + cc] =
                    make_float2(o[jj][0] * inv0, o[jj][1] * inv0);
                *(float2*)&out[((size_t)b * Tq + q0 + r0 + 8) * HSq + cc] =
                    make_float2(o[jj][2] * inv1, o[jj][3] * inv1);
            }
        } else {
            const int part = (kt0 == 0) ? 0 : 1;
            const size_t pb = (((size_t)b * 32 + qt) * 2 + part) * (64 * 128);
            const size_t mb = (((size_t)b * 32 + qt) * 2 + part) * 64;
            #pragma unroll
            for (int jj = 0; jj < 16; jj++) {
                int cc = 8 * jj + lc;
                *(float2*)&g_po[pb + (size_t)r0 * 128 + cc] = make_float2(o[jj][0], o[jj][1]);
                *(float2*)&g_po[pb + (size_t)(r0 + 8) * 128 + cc] = make_float2(o[jj][2], o[jj][3]);
            }
            if ((L & 3) == 0) {
                g_pm[mb + r0] = m0v;  g_pl[mb + r0] = l0v;
                g_pm[mb + r0 + 8] = m1v;  g_pl[mb + r0 + 8] = l1v;
            }
        }
        __syncthreads();
    }
}

// ---------------------------------------------------------------------------
// Kernel 3: merge partials for qt >= 16 (two parts each). Grid (16, 8).
// ---------------------------------------------------------------------------
__global__ __launch_bounds__(256) void merge_kernel(float* __restrict__ out)
{
    const int qt = 16 + blockIdx.x;
    const int b  = blockIdx.y;
    const int tid = threadIdx.x;
    const size_t base0 = (((size_t)b * 32 + qt) * 2 + 0) * (64 * 128);
    const size_t base1 = base0 + 64 * 128;
    const size_t mb0 = (((size_t)b * 32 + qt) * 2 + 0) * 64;
    const size_t mb1 = mb0 + 64;

    #pragma unroll
    for (int i = 0; i < 8; i++) {
        int idx = tid + i * 256;
        int off = idx * 4;
        int row = off >> 7;
        int col = off & 127;
        float4 a = *(const float4*)&g_po[base0 + off];
        float4 bb = *(const float4*)&g_po[base1 + off];
        float mA = g_pm[mb0 + row], lA = g_pl[mb0 + row];
        float mB = g_pm[mb1 + row], lB = g_pl[mb1 + row];
        float m = fmaxf(mA, mB);
        float wA = exp2f(mA - m), wB = exp2f(mB - m);
        float inv = __frcp_rn(lA * wA + lB * wB);
        float4 res = make_float4((a.x * wA + bb.x * wB) * inv,
                                 (a.y * wA + bb.y * wB) * inv,
                                 (a.z * wA + bb.z * wB) * inv,
                                 (a.w * wA + bb.w * wB) * inv);
        *(float4*)&out[((size_t)b * Tq + qt * 64 + row) * HSq + col] = res;
    }
}

// ---------------------------------------------------------------------------
extern "C" void kernel_launch(void* const* d_in, const int* in_sizes, int n_in,
                              void* d_out, int out_size)
{
    const float* x  = (const float*)d_in[0];
    const float* Wq = (const float*)d_in[1];
    const float* Wk = (const float*)d_in[2];
    const float* Wv = (const float*)d_in[3];
    float* out = (float*)d_out;

    cudaFuncSetAttribute(mega_kernel, cudaFuncAttributeMaxDynamicSharedMemorySize,
                         MEGA_SMEM);

    zero_kernel<<<1, 32>>>();

    prep_x_kernel<<<BT * Dq / (256 * 8), 256>>>(x);

    dim3 wgrid(Dq / 32, NTOT / 32);
    prep_w_kernel<<<wgrid, dim3(32, 8)>>>(Wq, Wk, Wv);

    mega_kernel<<<GRID_MEGA, 128, MEGA_SMEM>>>(out);

    dim3 mgrid(16, Bq);
    merge_kernel<<<mgrid, 256>>>(out);
}

// round 17
// speedup vs baseline: 1.1053x; 1.1053x over previous
#include <cuda_runtime.h>
#include <cuda_bf16.h>
#include <cuda_fp16.h>
#include <math.h>
#include <cstdint>

#define Bq   8
#define Tq   2048
#define Dq   1024
#define HSq  128
#define BT   (Bq * Tq)        // 16384 rows
#define NTOT 384              // 3 * HS

// Scratch (device globals — no allocs allowed). All operands single fp16.
__device__ __align__(256) __half g_wt_h[NTOT * Dq];          // W^T fp16 (Wq pre-scaled)
__device__ __align__(256) __half g_q[BT * HSq];              // q single fp16
__device__ __align__(256) __half g_k[BT * HSq];              // k single fp16
__device__ __align__(256) __half g_v[BT * HSq];              // v single fp16

// Split-KV partials: [b][qt][part][64][128] fp32 + per-row m,l (base-2 logits)
__device__ __align__(256) float g_po[Bq * 32 * 2 * 64 * 128];   // 16 MB
__device__ __align__(256) float g_pm[Bq * 32 * 2 * 64];
__device__ __align__(256) float g_pl[Bq * 32 * 2 * 64];

// Chunk LUT (48 chunks per batch), heavy-first (cnt descending).
__device__ const int c_qt[48]  = {15,16,17,18,19,20,21,22,23,24,25,26,27,28,29,30,31,31,
                                  14,30,13,29,12,28,11,27,10,26, 9,25, 8,24, 7,23,
                                   6,22, 5,21, 4,20, 3,19, 2,18, 1,17, 0,16};
__device__ const int c_k0[48]  = { 0, 0, 0, 0, 0, 0, 0, 0, 0, 0, 0, 0, 0, 0, 0, 0, 0,16,
                                   0,16, 0,16, 0,16, 0,16, 0,16, 0,16, 0,16, 0,16,
                                   0,16, 0,16, 0,16, 0,16, 0,16, 0,16, 0,16};
__device__ const int c_cnt[48] = {16,16,16,16,16,16,16,16,16,16,16,16,16,16,16,16,16,16,
                                  15,15,14,14,13,13,12,12,11,11,10,10, 9, 9, 8, 8,
                                   7, 7, 6, 6, 5, 5, 4, 4, 3, 3, 2, 2, 1, 1};

// ---------------------------------------------------------------------------
// Helpers
// ---------------------------------------------------------------------------
__device__ __forceinline__ void mma_f16(float* c, const uint32_t* a, const uint32_t* b) {
    asm volatile(
        "mma.sync.aligned.m16n8k16.row.col.f32.f16.f16.f32 "
        "{%0,%1,%2,%3}, {%4,%5,%6,%7}, {%8,%9}, {%0,%1,%2,%3};"
        : "+f"(c[0]), "+f"(c[1]), "+f"(c[2]), "+f"(c[3])
        : "r"(a[0]), "r"(a[1]), "r"(a[2]), "r"(a[3]), "r"(b[0]), "r"(b[1]));
}
__device__ __forceinline__ void ldsm_x4(uint32_t* r, uint32_t addr) {
    asm volatile("ldmatrix.sync.aligned.m8n8.x4.shared.b16 {%0,%1,%2,%3}, [%4];"
                 : "=r"(r[0]), "=r"(r[1]), "=r"(r[2]), "=r"(r[3]) : "r"(addr));
}
__device__ __forceinline__ void ldsm_x4_t(uint32_t* r, uint32_t addr) {
    asm volatile("ldmatrix.sync.aligned.m8n8.x4.trans.shared.b16 {%0,%1,%2,%3}, [%4];"
                 : "=r"(r[0]), "=r"(r[1]), "=r"(r[2]), "=r"(r[3]) : "r"(addr));
}
__device__ __forceinline__ uint32_t smem_u32(const void* p) {
    uint32_t a;
    asm("{ .reg .u64 t; cvta.to.shared.u64 t, %1; cvt.u32.u64 %0, t; }"
        : "=r"(a) : "l"(p));
    return a;
}
__device__ __forceinline__ void cp16(uint32_t dst, const void* src) {
    asm volatile("cp.async.cg.shared.global [%0], [%1], 16;" :: "r"(dst), "l"(src));
}
#define CP_COMMIT() asm volatile("cp.async.commit_group;" ::: "memory")
#define CP_WAIT0()  asm volatile("cp.async.wait_group 0;" ::: "memory")
#define CP_WAIT1()  asm volatile("cp.async.wait_group 1;" ::: "memory")

__device__ __forceinline__ uint32_t packh2(float v0, float v1) {
    __half2 h2 = __floats2half2_rn(v0, v1);
    return *(uint32_t*)&h2;
}

// ---------------------------------------------------------------------------
// Kernel 0b: transpose + convert weights to fp16 (Wq scaled by 128^-0.5*log2e).
// ---------------------------------------------------------------------------
__global__ void prep_w_kernel(const float* __restrict__ Wq,
                              const float* __restrict__ Wk,
                              const float* __restrict__ Wv)
{
    __shared__ float t[32][33];
    const int k0 = blockIdx.x * 32;
    const int n0 = blockIdx.y * 32;
    const int slab = n0 >> 7;
    const float* W = (slab == 0) ? Wq : (slab == 1) ? Wk : Wv;
    const float sc = (slab == 0) ? (0.08838834764831845f * 1.4426950408889634f) : 1.0f;
    const int nn0 = n0 & 127;
    const int tx = threadIdx.x, ty = threadIdx.y;

    #pragma unroll
    for (int i = 0; i < 4; i++)
        t[ty * 4 + i][tx] = W[(size_t)(k0 + ty * 4 + i) * HSq + nn0 + tx] * sc;
    __syncthreads();
    #pragma unroll
    for (int i = 0; i < 4; i++) {
        int nr = ty * 4 + i;
        g_wt_h[(size_t)(n0 + nr) * Dq + k0 + tx] = __float2half_rn(t[tx][nr]);
    }
}

// ---------------------------------------------------------------------------
// Kernel 1: QKV projection, single-fp16 HMMA, fused fp32->fp16 X conversion.
// X read as fp32 from input, converted in registers, STS'd as fp16.
// W via cp.async (fp16, pre-converted). BK=64 (16 chunks).
// Grid (128 M-tiles, 3 slabs), block 256 (8 warps, 4x2). BM=128 BN=128.
// ---------------------------------------------------------------------------
#define PS      144           // smem row pitch bytes (64 fp16 data + 8 pad)
#define P_ARR   (128 * PS)    // 18432
#define P_XH    0
#define P_WH    (1 * P_ARR)
#define P_BUF   (2 * P_ARR)   // 36864
#define PROJ_SMEM (2 * P_BUF) // 73728

__global__ __launch_bounds__(256, 2) void proj_mma_kernel(const float* __restrict__ x)
{
    extern __shared__ __align__(16) char smc[];
    const uint32_t sb = smem_u32(smc);
    const int tid = threadIdx.x;
    const int w   = tid >> 5;
    const int L   = tid & 31;
    const int m0  = blockIdx.x * 128;
    const int nt  = blockIdx.y;                   // 0:q 1:k 2:v

    const __half* wh = g_wt_h + (size_t)nt * HSq * Dq;
    const float*  xf = x + (size_t)m0 * Dq;
    __half* outp = (nt == 0) ? g_q : (nt == 1) ? g_k : g_v;

    const int mrow  = (w & 3) * 32;
    const int nbase = (w >> 2) * 64;

    // X staging: per chunk each thread owns 8 float4 (= one row-segment pattern)
    // idx = tid + i*256, i in 0..7; row = idx >> 4 (16 float4 per 64-fp32 row),
    // q = idx & 15. Converted to 16 packed-u32 (fp16x2).
    const int xrow[8] = { (tid + 0*256) >> 4, (tid + 1*256) >> 4, (tid + 2*256) >> 4,
                          (tid + 3*256) >> 4, (tid + 4*256) >> 4, (tid + 5*256) >> 4,
                          (tid + 6*256) >> 4, (tid + 7*256) >> 4 };
    const int xq = tid & 15;   // same for all i since 256 % 16 == 0

    uint32_t xr[16];
    auto load_x = [&](int ch) {
        const int kb = ch * 64;
        #pragma unroll
        for (int i = 0; i < 8; i++) {
            float4 v = *(const float4*)&xf[(size_t)xrow[i] * Dq + kb + xq * 4];
            xr[2 * i]     = packh2(v.x, v.y);
            xr[2 * i + 1] = packh2(v.z, v.w);
        }
    };
    auto sts_x = [&](uint32_t bb) {
        #pragma unroll
        for (int i = 0; i < 8; i++) {
            *(uint2*)(smc + (bb - sb) + P_XH + xrow[i] * PS + xq * 8) =
                make_uint2(xr[2 * i], xr[2 * i + 1]);
        }
    };
    auto cp_w = [&](int ch, uint32_t bb) {
        const int kb = ch * 64;
        #pragma unroll
        for (int i = 0; i < 4; i++) {
            int idx = tid + i * 256;
            int r = idx >> 3, q = idx & 7;        // 8 x 16B = 128 bytes/row
            cp16(bb + P_WH + r * PS + q * 16, wh + (size_t)r * Dq + kb + q * 8);
        }
    };

    float c[2][8][4];
    #pragma unroll
    for (int mt = 0; mt < 2; mt++)
        #pragma unroll
        for (int j = 0; j < 8; j++)
            #pragma unroll
            for (int r = 0; r < 4; r++) c[mt][j][r] = 0.f;

    load_x(0);
    cp_w(0, sb);
    CP_COMMIT();

    for (int ch = 0; ch < Dq / 64; ch++) {
        const uint32_t base = sb + (ch & 1) * P_BUF;

        // Store this chunk's X (registers -> fp16 smem). Safe: buf (ch&1) was
        // last read by MMA(ch-2), guarded by two intervening barriers.
        sts_x(base);
        if (ch + 1 < Dq / 64) {
            cp_w(ch + 1, sb + ((ch + 1) & 1) * P_BUF);
            CP_COMMIT();
            CP_WAIT1();       // W(ch) complete
        } else {
            CP_WAIT0();
        }
        __syncthreads();      // X STS + W cp.async visible to all warps

        if (ch + 1 < Dq / 64) load_x(ch + 1);   // LDGs hidden under MMA section

        // A fragments: 2 mt x 4 k-steps, each ldsm.x4 = one 16x16 A fragment
        uint32_t ah[2][4][4];
        #pragma unroll
        for (int mt = 0; mt < 2; mt++) {
            uint32_t arow = base + P_XH
                + (uint32_t)(mrow + mt * 16 + (L & 7) + ((L >> 3) & 1) * 8) * PS
                + (L >> 4) * 16;
            #pragma unroll
            for (int ks = 0; ks < 4; ks++)
                ldsm_x4(ah[mt][ks], arow + ks * 32);
        }

        #pragma unroll
        for (int j = 0; j < 8; j++) {
            uint32_t brow = base + P_WH
                + (uint32_t)(nbase + 8 * j + (L & 7)) * PS + ((L >> 3) & 3) * 16;
            uint32_t bh[4], bh2[4];
            ldsm_x4(bh, brow);          // k 0-31
            ldsm_x4(bh2, brow + 64);    // k 32-63
            #pragma unroll
            for (int mt = 0; mt < 2; mt++) {
                mma_f16(c[mt][j], ah[mt][0], bh);
                mma_f16(c[mt][j], ah[mt][1], bh + 2);
                mma_f16(c[mt][j], ah[mt][2], bh2);
                mma_f16(c[mt][j], ah[mt][3], bh2 + 2);
            }
        }
        __syncthreads();
    }

    // Epilogue: single fp16 pack for q, k, v
    const int lr = L >> 2;
    const int lc = (L & 3) * 2;
    #pragma unroll
    for (int mt = 0; mt < 2; mt++) {
        int r0 = m0 + mrow + mt * 16 + lr;
        #pragma unroll
        for (int j = 0; j < 8; j++) {
            int cc = nbase + 8 * j + lc;
            *(uint32_t*)&outp[(size_t)r0 * HSq + cc] = packh2(c[mt][j][0], c[mt][j][1]);
            *(uint32_t*)&outp[(size_t)(r0 + 8) * HSq + cc] = packh2(c[mt][j][2], c[mt][j][3]);
        }
    }
}

// ---------------------------------------------------------------------------
// Kernel 2: split-KV causal flash attention, single-fp16 everywhere (1-term).
// S = Q*K; O = P*V. K double-buffered, V single-buffered. smem 52224, 2 CTAs/SM.
// Grid (8 batch, 48 chunks heavy-first). Block 128 (4 warps).
// ---------------------------------------------------------------------------
#define KV_ROWB 272                        // 128 fp16 data + 8 pad
#define KTILE   (64 * KV_ROWB)             // 17408
#define A_K0    0
#define A_K1    (1 * KTILE)
#define A_V     (2 * KTILE)
#define ATTN_SMEM (3 * KTILE)              // 52224

__global__ __launch_bounds__(128, 2) void attn_mma_kernel(float* __restrict__ out)
{
    extern __shared__ __align__(16) char smc[];
    const uint32_t sb = smem_u32(smc);
    const int tid = threadIdx.x;
    const int w   = tid >> 5;
    const int L   = tid & 31;
    const int b   = blockIdx.x;
    const int cid = blockIdx.y;
    const int qt  = c_qt[cid];
    const int kt0 = c_k0[cid];
    const int cnt = c_cnt[cid];
    const int q0  = qt * 64;

    const __half* q_g = g_q + (size_t)b * Tq * HSq;
    const __half* k_g = g_k + (size_t)b * Tq * HSq;
    const __half* v_g = g_v + (size_t)b * Tq * HSq;

    const int lr = L >> 2;
    const int lc = (L & 3) * 2;

    auto prefetch_k = [&](int krow, int buf) {
        uint32_t kb = sb + (buf ? A_K1 : A_K0);
        #pragma unroll
        for (int i = 0; i < 8; i++) {
            int idx = tid + i * 128;
            int r = idx >> 4, q = idx & 15;
            cp16(kb + r * KV_ROWB + q * 16, k_g + (size_t)(krow + r) * HSq + q * 8);
        }
    };
    auto prefetch_v = [&](int krow) {
        #pragma unroll
        for (int i = 0; i < 8; i++) {
            int idx = tid + i * 128;
            int r = idx >> 4, q = idx & 15;
            cp16(sb + A_V + r * KV_ROWB + q * 16, v_g + (size_t)(krow + r) * HSq + q * 8);
        }
    };

    // Q fragments (pre-scaled by 128^-0.5*log2e), single fp16
    uint32_t qh[8][4];
    #pragma unroll
    for (int s = 0; s < 8; s++)
        #pragma unroll
        for (int i = 0; i < 4; i++) {
            int rr = q0 + 16 * w + lr + 8 * (i & 1);
            int cc = 16 * s + lc + 8 * (i >> 1);
            qh[s][i] = *(const uint32_t*)&q_g[(size_t)rr * HSq + cc];
        }

    float o[16][4];
    #pragma unroll
    for (int j = 0; j < 16; j++)
        #pragma unroll
        for (int r = 0; r < 4; r++) o[j][r] = 0.f;
    float m0v = -1e30f, m1v = -1e30f, l0v = 0.f, l1v = 0.f;

    prefetch_k(kt0 * 64, 0); CP_COMMIT();
    prefetch_v(kt0 * 64);    CP_COMMIT();

    for (int t = 0; t < cnt; t++) {
        const int tile = kt0 + t;
        CP_WAIT1();           // K(t) complete
        __syncthreads();
        if (t + 1 < cnt) { prefetch_k((tile + 1) * 64, (t + 1) & 1); CP_COMMIT(); }

        const uint32_t kbuf = sb + ((t & 1) ? A_K1 : A_K0);

        // S = Q K^T : single-fp16 1-term
        float c[8][4];
        #pragma unroll
        for (int j = 0; j < 8; j++) {
            c[j][0] = c[j][1] = c[j][2] = c[j][3] = 0.f;
            uint32_t rowaddr = kbuf + (8 * j + (L & 7)) * KV_ROWB + ((L >> 3) & 3) * 16;
            #pragma unroll
            for (int sp = 0; sp < 4; sp++) {
                uint32_t bh[4];
                ldsm_x4(bh, rowaddr + 64 * sp);
                mma_f16(c[j], qh[2 * sp],     bh);
                mma_f16(c[j], qh[2 * sp + 1], bh + 2);
            }
        }

        // Causal mask on diagonal tile
        if (tile == qt) {
            int r0 = 16 * w + lr, r1 = r0 + 8;
            #pragma unroll
            for (int j = 0; j < 8; j++) {
                int n0 = 8 * j + lc;
                if (n0 > r0)     c[j][0] = -1e30f;
                if (n0 + 1 > r0) c[j][1] = -1e30f;
                if (n0 > r1)     c[j][2] = -1e30f;
                if (n0 + 1 > r1) c[j][3] = -1e30f;
            }
        }

        // Online softmax (base-2); P packed to single fp16
        float mx0 = -1e30f, mx1 = -1e30f;
        #pragma unroll
        for (int j = 0; j < 8; j++) {
            mx0 = fmaxf(mx0, fmaxf(c[j][0], c[j][1]));
            mx1 = fmaxf(mx1, fmaxf(c[j][2], c[j][3]));
        }
        #pragma unroll
        for (int off = 1; off <= 2; off <<= 1) {
            mx0 = fmaxf(mx0, __shfl_xor_sync(0xffffffffu, mx0, off));
            mx1 = fmaxf(mx1, __shfl_xor_sync(0xffffffffu, mx1, off));
        }
        float mn0 = fmaxf(m0v, mx0), mn1 = fmaxf(m1v, mx1);
        float a0 = exp2f(m0v - mn0), a1 = exp2f(m1v - mn1);
        float rs0 = 0.f, rs1 = 0.f;
        uint32_t ph[8][2];
        #pragma unroll
        for (int j = 0; j < 8; j++) {
            float p0 = exp2f(c[j][0] - mn0);
            float p1 = exp2f(c[j][1] - mn0);
            float p2 = exp2f(c[j][2] - mn1);
            float p3 = exp2f(c[j][3] - mn1);
            rs0 += p0 + p1; rs1 += p2 + p3;
            ph[j][0] = packh2(p0, p1);
            ph[j][1] = packh2(p2, p3);
        }
        #pragma unroll
        for (int off = 1; off <= 2; off <<= 1) {
            rs0 += __shfl_xor_sync(0xffffffffu, rs0, off);
            rs1 += __shfl_xor_sync(0xffffffffu, rs1, off);
        }
        l0v = l0v * a0 + rs0;  m0v = mn0;
        l1v = l1v * a1 + rs1;  m1v = mn1;
        #pragma unroll
        for (int j = 0; j < 16; j++) {
            o[j][0] *= a0; o[j][1] *= a0;
            o[j][2] *= a1; o[j][3] *= a1;
        }

        // Wait for V(t)
        if (t + 1 < cnt) { CP_WAIT1(); } else { CP_WAIT0(); }
        __syncthreads();

        // O += P V : single-fp16 (1-term)
        #pragma unroll
        for (int s = 0; s < 4; s++) {
            uint32_t ap[4] = { ph[2*s][0], ph[2*s][1], ph[2*s+1][0], ph[2*s+1][1] };
            uint32_t vaddr = sb + A_V + (16 * s + (L & 15)) * KV_ROWB + (L >> 4) * 16;
            #pragma unroll
            for (int jj = 0; jj < 16; jj += 2) {
                uint32_t bh[4];
                ldsm_x4_t(bh, vaddr + 16 * jj);
                mma_f16(o[jj],     ap, bh);
                mma_f16(o[jj + 1], ap, bh + 2);
            }
        }

        __syncthreads();
        if (t + 1 < cnt) { prefetch_v((tile + 1) * 64); CP_COMMIT(); }
    }

    const bool full = (kt0 == 0) && (cnt == qt + 1);   // covers entire causal range
    int r0 = 16 * w + lr;
    if (full) {
        float inv0 = __frcp_rn(l0v), inv1 = __frcp_rn(l1v);
        #pragma unroll
        for (int jj = 0; jj < 16; jj++) {
            int cc = 8 * jj + lc;
            *(float2*)&out[((size_t)b * Tq + q0 + r0) * HSq + cc] =
                make_float2(o[jj][0] * inv0, o[jj][1] * inv0);
            *(float2*)&out[((size_t)b * Tq + q0 + r0 + 8) * HSq + cc] =
                make_float2(o[jj][2] * inv1, o[jj][3] * inv1);
        }
    } else {
        const int part = (kt0 == 0) ? 0 : 1;
        const size_t pb = (((size_t)b * 32 + qt) * 2 + part) * (64 * 128);
        const size_t mb = (((size_t)b * 32 + qt) * 2 + part) * 64;
        #pragma unroll
        for (int jj = 0; jj < 16; jj++) {
            int cc = 8 * jj + lc;
            *(float2*)&g_po[pb + (size_t)r0 * 128 + cc] = make_float2(o[jj][0], o[jj][1]);
            *(float2*)&g_po[pb + (size_t)(r0 + 8) * 128 + cc] = make_float2(o[jj][2], o[jj][3]);
        }
        if ((L & 3) == 0) {
            g_pm[mb + r0] = m0v;  g_pl[mb + r0] = l0v;
            g_pm[mb + r0 + 8] = m1v;  g_pl[mb + r0 + 8] = l1v;
        }
    }
}

// ---------------------------------------------------------------------------
// Kernel 3: merge partials for qt >= 16 (two parts each). Grid (16, 8).
// ---------------------------------------------------------------------------
__global__ __launch_bounds__(256) void merge_kernel(float* __restrict__ out)
{
    const int qt = 16 + blockIdx.x;
    const int b  = blockIdx.y;
    const int tid = threadIdx.x;
    const size_t base0 = (((size_t)b * 32 + qt) * 2 + 0) * (64 * 128);
    const size_t base1 = base0 + 64 * 128;
    const size_t mb0 = (((size_t)b * 32 + qt) * 2 + 0) * 64;
    const size_t mb1 = mb0 + 64;

    #pragma unroll
    for (int i = 0; i < 8; i++) {
        int idx = tid + i * 256;        // float4 index, 2048 total
        int off = idx * 4;
        int row = off >> 7;
        int col = off & 127;
        float4 a = *(const float4*)&g_po[base0 + off];
        float4 bb = *(const float4*)&g_po[base1 + off];
        float mA = g_pm[mb0 + row], lA = g_pl[mb0 + row];
        float mB = g_pm[mb1 + row], lB = g_pl[mb1 + row];
        float m = fmaxf(mA, mB);
        float wA = exp2f(mA - m), wB = exp2f(mB - m);
        float inv = __frcp_rn(lA * wA + lB * wB);
        float4 res = make_float4((a.x * wA + bb.x * wB) * inv,
                                 (a.y * wA + bb.y * wB) * inv,
                                 (a.z * wA + bb.z * wB) * inv,
                                 (a.w * wA + bb.w * wB) * inv);
        *(float4*)&out[((size_t)b * Tq + qt * 64 + row) * HSq + col] = res;
    }
}

// ---------------------------------------------------------------------------
extern "C" void kernel_launch(void* const* d_in, const int* in_sizes, int n_in,
                              void* d_out, int out_size)
{
    const float* x  = (const float*)d_in[0];
    const float* Wq = (const float*)d_in[1];
    const float* Wk = (const float*)d_in[2];
    const float* Wv = (const float*)d_in[3];
    float* out = (float*)d_out;

    cudaFuncSetAttribute(proj_mma_kernel, cudaFuncAttributeMaxDynamicSharedMemorySize,
                         PROJ_SMEM);
    cudaFuncSetAttribute(attn_mma_kernel, cudaFuncAttributeMaxDynamicSharedMemorySize,
                         ATTN_SMEM);

    dim3 wgrid(Dq / 32, NTOT / 32);
    prep_w_kernel<<<wgrid, dim3(32, 8)>>>(Wq, Wk, Wv);

    dim3 pgrid(BT / 128, 3);
    proj_mma_kernel<<<pgrid, 256, PROJ_SMEM>>>(x);

    dim3 agrid(Bq, 48);
    attn_mma_kernel<<<agrid, 128, ATTN_SMEM>>>(out);

    dim3 mgrid(16, Bq);
    merge_kernel<<<mgrid, 256>>>(out);
}